// round 3
// baseline (speedup 1.0000x reference)
#include <cuda_runtime.h>
#include <cuda_bf16.h>
#include <math.h>

// Problem constants
#define BATCH 2
#define DIM   256
#define HW    64
#define LSEQ  4096          // 64*64
#define BL    8192          // BATCH*LSEQ
#define DI    512           // d_inner
#define NST   16            // d_state
#define RNK   16            // dt_rank
#define XZW   1024          // 2*DI
#define HIDW  1024          // 4*DIM

// ---------------- scratch (static device globals; no allocation) -------------
__device__ float g_yn  [(size_t)BL * DIM];   // layernorm output (B,L,C)
__device__ float g_xz  [(size_t)BL * XZW];   // xz projection (xm | z)
__device__ float g_u   [(size_t)BL * DI];    // conv+silu output
__device__ float g_proj[(size_t)BL * 48];    // dt_raw(16) | B(16) | C(16)
__device__ float g_dt  [(size_t)BL * DI];    // softplus dt
__device__ float g_ym  [(size_t)BL * DI];    // scan output ys, then gated ym
__device__ float g_y2  [(size_t)BL * DIM];
__device__ float g_hid [(size_t)BL * HIDW];
__device__ float g_y3  [(size_t)BL * DIM];

// ---------------- transpose: in (B, D1, D2) -> out (B, D2, D1) ---------------
__global__ void k_transpose(const float* __restrict__ in, float* __restrict__ out,
                            int D1, int D2) {
    __shared__ float tile[32][33];
    int b  = blockIdx.z;
    int i0 = blockIdx.y * 32;   // along D1
    int j0 = blockIdx.x * 32;   // along D2
    int tx = threadIdx.x, ty = threadIdx.y;
    const float* ip = in  + (size_t)b * D1 * D2;
    float*       op = out + (size_t)b * D1 * D2;
#pragma unroll
    for (int s = 0; s < 32; s += 8)
        tile[ty + s][tx] = ip[(size_t)(i0 + ty + s) * D2 + j0 + tx];
    __syncthreads();
#pragma unroll
    for (int s = 0; s < 32; s += 8)
        op[(size_t)(j0 + ty + s) * D1 + i0 + tx] = tile[tx][ty + s];
}

// ---------------- layernorm (in place on (BL, 256) rows), warp per row -------
__global__ void k_layernorm(float* __restrict__ y,
                            const float* __restrict__ gamma,
                            const float* __restrict__ beta) {
    int gw   = (blockIdx.x * blockDim.x + threadIdx.x) >> 5;
    int lane = threadIdx.x & 31;
    if (gw >= BL) return;
    float* row = y + (size_t)gw * DIM;
    float v[8];
    float s = 0.f;
#pragma unroll
    for (int t = 0; t < 8; t++) { v[t] = row[lane + 32 * t]; s += v[t]; }
#pragma unroll
    for (int o = 16; o > 0; o >>= 1) s += __shfl_xor_sync(~0u, s, o);
    float mu = s * (1.f / DIM);
    float var = 0.f;
#pragma unroll
    for (int t = 0; t < 8; t++) { float d = v[t] - mu; var += d * d; }
#pragma unroll
    for (int o = 16; o > 0; o >>= 1) var += __shfl_xor_sync(~0u, var, o);
    float rstd = rsqrtf(var * (1.f / DIM) + 1e-5f);
#pragma unroll
    for (int t = 0; t < 8; t++) {
        int c = lane + 32 * t;
        row[c] = (v[t] - mu) * rstd * gamma[c] + beta[c];
    }
}

// ---------------- causal depthwise conv(4) + silu ----------------------------
__global__ void k_conv_silu(const float* __restrict__ xz,
                            const float* __restrict__ cw,
                            const float* __restrict__ cb,
                            float* __restrict__ u) {
    int i = blockIdx.x * blockDim.x + threadIdx.x;
    if (i >= BL * DI) return;
    int d    = i & (DI - 1);
    int lrow = i >> 9;          // (b*L + l)
    int l    = lrow & (LSEQ - 1);
    float acc = cb[d];
#pragma unroll
    for (int k = 0; k < 4; k++) {
        int ll = l - 3 + k;
        if (ll >= 0)
            acc += cw[d * 4 + k] * xz[(size_t)(lrow - 3 + k) * XZW + d];
    }
    u[i] = acc / (1.f + __expf(-acc));   // silu
}

// ---------------- x-proj: proj(BL,48) = u(BL,512) @ W_xp(48,512)^T ----------
__global__ void k_proj(const float* __restrict__ u,
                       const float* __restrict__ Wxp,
                       float* __restrict__ proj) {
    int gw   = (blockIdx.x * blockDim.x + threadIdx.x) >> 5;
    int lane = threadIdx.x & 31;
    if (gw >= BL) return;
    const float* ur = u + (size_t)gw * DI;
    float ureg[16];
#pragma unroll
    for (int t = 0; t < 16; t++) ureg[t] = ur[lane + 32 * t];
    for (int j = 0; j < 48; j++) {
        const float* w = Wxp + (size_t)j * DI;
        float s = 0.f;
#pragma unroll
        for (int t = 0; t < 16; t++) s += ureg[t] * w[lane + 32 * t];
#pragma unroll
        for (int o = 16; o > 0; o >>= 1) s += __shfl_xor_sync(~0u, s, o);
        if (lane == 0) proj[(size_t)gw * 48 + j] = s;
    }
}

// ---------------- dt = softplus(proj[:, :16] @ W_dt^T + b_dt) ----------------
__global__ void k_dt(const float* __restrict__ proj,
                     const float* __restrict__ Wdt,
                     const float* __restrict__ bdt,
                     float* __restrict__ dt) {
    __shared__ float p[16];
    int i = blockIdx.x;
    int d = threadIdx.x;
    if (d < 16) p[d] = proj[(size_t)i * 48 + d];
    __syncthreads();
    const float4* w4 = (const float4*)(Wdt + d * 16);
    float s = bdt[d];
#pragma unroll
    for (int r4 = 0; r4 < 4; r4++) {
        float4 w = w4[r4];
        s += p[r4 * 4 + 0] * w.x + p[r4 * 4 + 1] * w.y +
             p[r4 * 4 + 2] * w.z + p[r4 * 4 + 3] * w.w;
    }
    float sp = fmaxf(s, 0.f) + log1pf(__expf(-fabsf(s)));
    dt[(size_t)i * DI + d] = sp;
}

// ---------------- selective scan ---------------------------------------------
// thread = (b, d, n); block = 8 d-channels x 16 states; grid = B * DI/8
#define ST 128
__global__ void __launch_bounds__(128) k_scan(
    const float* __restrict__ dt, const float* __restrict__ u,
    const float* __restrict__ proj, const float* __restrict__ A_log,
    float* __restrict__ ys) {
    __shared__ float sdt[ST * 8], su[ST * 8], sB[ST * 16], sC[ST * 16], sy[ST * 8];
    int blk = blockIdx.x;
    int b   = blk >> 6;
    int d0  = (blk & 63) * 8;
    int tid  = threadIdx.x;
    int dloc = tid >> 4;
    int n    = tid & 15;
    int d    = d0 + dloc;
    float a = -__expf(A_log[d * NST + n]);
    float h = 0.f;
    size_t base = (size_t)b * LSEQ;
    for (int l0 = 0; l0 < LSEQ; l0 += ST) {
        __syncthreads();
        for (int idx = tid; idx < ST * 8; idx += 128) {
            int j = idx >> 3, dd = idx & 7;
            size_t g = (base + l0 + j) * DI + d0 + dd;
            sdt[idx] = dt[g];
            su[idx]  = u[g];
        }
        for (int idx = tid; idx < ST * 16; idx += 128) {
            int j = idx >> 4, nn = idx & 15;
            size_t g = (base + l0 + j) * 48;
            sB[idx] = proj[g + 16 + nn];
            sC[idx] = proj[g + 32 + nn];
        }
        __syncthreads();
#pragma unroll 4
        for (int j = 0; j < ST; j++) {
            float dtv = sdt[j * 8 + dloc];
            float dA  = __expf(dtv * a);
            h = dA * h + (dtv * su[j * 8 + dloc]) * sB[j * 16 + n];
            float yv = h * sC[j * 16 + n];
            yv += __shfl_xor_sync(~0u, yv, 8);
            yv += __shfl_xor_sync(~0u, yv, 4);
            yv += __shfl_xor_sync(~0u, yv, 2);
            yv += __shfl_xor_sync(~0u, yv, 1);
            if (n == 0) sy[j * 8 + dloc] = yv;
        }
        __syncthreads();
        for (int idx = tid; idx < ST * 8; idx += 128) {
            int j = idx >> 3, dd = idx & 7;
            ys[(base + l0 + j) * DI + d0 + dd] = sy[idx];
        }
    }
}

// ---------------- gate: ym = (ys + u*D) * silu(z) ----------------------------
__global__ void k_gate(float* __restrict__ ym, const float* __restrict__ u,
                       const float* __restrict__ xz, const float* __restrict__ Dv) {
    int i = blockIdx.x * blockDim.x + threadIdx.x;
    if (i >= BL * DI) return;
    int d   = i & (DI - 1);
    int row = i >> 9;
    float zv  = xz[(size_t)row * XZW + DI + d];
    float sil = zv / (1.f + __expf(-zv));
    ym[i] = (ym[i] + u[i] * Dv[d]) * sil;
}

// ---------------- SGEMM: C(M,N) = A(M,K) @ Bw(N,K)^T (+ epilogue) -----------
// EPI: 0 none; 1 bias+gelu; 2 +resid; 3 bias+resid
template <int EPI>
__global__ void __launch_bounds__(256) k_sgemm(
    const float* __restrict__ A, const float* __restrict__ Bw,
    const float* __restrict__ bias, const float* __restrict__ resid,
    float* __restrict__ C, int M, int N, int K) {
    __shared__ float As[8][128];
    __shared__ float Bs[8][128];
    int tid = threadIdx.x;
    int tx = tid & 15, ty = tid >> 4;
    int row0 = blockIdx.y * 128, col0 = blockIdx.x * 128;
    int lr = tid >> 1;
    int lk = (tid & 1) * 4;
    const float* Aptr = A  + (size_t)(row0 + lr) * K + lk;
    const float* Bptr = Bw + (size_t)(col0 + lr) * K + lk;
    float acc[8][8];
#pragma unroll
    for (int i = 0; i < 8; i++)
#pragma unroll
        for (int j = 0; j < 8; j++) acc[i][j] = 0.f;

    // prefetch first tile
    float4 av = *(const float4*)(Aptr);
    float4 bv = *(const float4*)(Bptr);

    for (int kt = 0; kt < K; kt += 8) {
        As[lk + 0][lr] = av.x; As[lk + 1][lr] = av.y;
        As[lk + 2][lr] = av.z; As[lk + 3][lr] = av.w;
        Bs[lk + 0][lr] = bv.x; Bs[lk + 1][lr] = bv.y;
        Bs[lk + 2][lr] = bv.z; Bs[lk + 3][lr] = bv.w;
        __syncthreads();
        // prefetch next tile while computing this one
        if (kt + 8 < K) {
            av = *(const float4*)(Aptr + kt + 8);
            bv = *(const float4*)(Bptr + kt + 8);
        }
#pragma unroll
        for (int k = 0; k < 8; k++) {
            float4 a0 = *(const float4*)&As[k][ty * 8];
            float4 a1 = *(const float4*)&As[k][ty * 8 + 4];
            float4 b0 = *(const float4*)&Bs[k][tx * 8];
            float4 b1 = *(const float4*)&Bs[k][tx * 8 + 4];
            float ar[8] = {a0.x, a0.y, a0.z, a0.w, a1.x, a1.y, a1.z, a1.w};
            float br[8] = {b0.x, b0.y, b0.z, b0.w, b1.x, b1.y, b1.z, b1.w};
#pragma unroll
            for (int i = 0; i < 8; i++)
#pragma unroll
                for (int j = 0; j < 8; j++) acc[i][j] += ar[i] * br[j];
        }
        __syncthreads();
    }
#pragma unroll
    for (int i = 0; i < 8; i++) {
        int r = row0 + ty * 8 + i;
#pragma unroll
        for (int j = 0; j < 8; j++) {
            int c = col0 + tx * 8 + j;
            float v = acc[i][j];
            if (EPI == 1) {
                v += bias[c];
                v = 0.5f * v * (1.f + erff(v * 0.70710678118654752f));
            } else if (EPI == 2) {
                v += resid[(size_t)r * N + c];
            } else if (EPI == 3) {
                v += bias[c] + resid[(size_t)r * N + c];
            }
            C[(size_t)r * N + c] = v;
        }
    }
}

// ---------------- launcher ---------------------------------------------------
extern "C" void kernel_launch(void* const* d_in, const int* in_sizes, int n_in,
                              void* d_out, int out_size) {
    const float* x      = (const float*)d_in[0];
    const float* gamma  = (const float*)d_in[1];
    const float* beta   = (const float*)d_in[2];
    const float* W_in   = (const float*)d_in[3];
    const float* conv_w = (const float*)d_in[4];
    const float* conv_b = (const float*)d_in[5];
    const float* W_xp   = (const float*)d_in[6];
    const float* W_dt   = (const float*)d_in[7];
    const float* b_dt   = (const float*)d_in[8];
    const float* A_log  = (const float*)d_in[9];
    const float* Dv     = (const float*)d_in[10];
    const float* W_out  = (const float*)d_in[11];
    const float* W1     = (const float*)d_in[12];
    const float* b1     = (const float*)d_in[13];
    const float* W2     = (const float*)d_in[14];
    const float* b2     = (const float*)d_in[15];
    float* out = (float*)d_out;

    float *yn, *xz, *u, *proj, *dt, *ym, *y2, *hid, *y3;
    cudaGetSymbolAddress((void**)&yn,  g_yn);
    cudaGetSymbolAddress((void**)&xz,  g_xz);
    cudaGetSymbolAddress((void**)&u,   g_u);
    cudaGetSymbolAddress((void**)&proj,g_proj);
    cudaGetSymbolAddress((void**)&dt,  g_dt);
    cudaGetSymbolAddress((void**)&ym,  g_ym);
    cudaGetSymbolAddress((void**)&y2,  g_y2);
    cudaGetSymbolAddress((void**)&hid, g_hid);
    cudaGetSymbolAddress((void**)&y3,  g_y3);

    dim3 tb(32, 8);

    // 1) transpose x (B,C,L) -> yn (B,L,C)
    {
        dim3 grid(LSEQ / 32, DIM / 32, BATCH);
        k_transpose<<<grid, tb>>>(x, yn, DIM, LSEQ);
    }
    // 2) layernorm in place
    k_layernorm<<<BL * 32 / 256, 256>>>(yn, gamma, beta);
    // 3) xz = yn @ W_in^T  (8192 x 1024 x 256)
    {
        dim3 grid(XZW / 128, BL / 128);
        k_sgemm<0><<<grid, 256>>>(yn, W_in, nullptr, nullptr, xz, BL, XZW, DIM);
    }
    // 4) conv + silu -> u
    k_conv_silu<<<(BL * DI) / 256, 256>>>(xz, conv_w, conv_b, u);
    // 5) proj = u @ W_xp^T
    k_proj<<<BL / 8, 256>>>(u, W_xp, proj);
    // 6) dt
    k_dt<<<BL, DI>>>(proj, W_dt, b_dt, dt);
    // 7) selective scan -> ym (holds ys)
    k_scan<<<BATCH * (DI / 8), 128>>>(dt, u, proj, A_log, ym);
    // 8) gate
    k_gate<<<(BL * DI) / 256, 256>>>(ym, u, xz, Dv);
    // 9) y2 = ym @ W_out^T + yn   (8192 x 256 x 512)
    {
        dim3 grid(DIM / 128, BL / 128);
        k_sgemm<2><<<grid, 256>>>(ym, W_out, nullptr, yn, y2, BL, DIM, DI);
    }
    // 10) hid = gelu(y2 @ W1^T + b1)   (8192 x 1024 x 256)
    {
        dim3 grid(HIDW / 128, BL / 128);
        k_sgemm<1><<<grid, 256>>>(y2, W1, b1, nullptr, hid, BL, HIDW, DIM);
    }
    // 11) y3 = hid @ W2^T + b2 + y2   (8192 x 256 x 1024)
    {
        dim3 grid(DIM / 128, BL / 128);
        k_sgemm<3><<<grid, 256>>>(hid, W2, b2, y2, y3, BL, DIM, HIDW);
    }
    // 12) transpose y3 (B,L,C) -> out (B,C,L)
    {
        dim3 grid(DIM / 32, LSEQ / 32, BATCH);
        k_transpose<<<grid, tb>>>(y3, out, LSEQ, DIM);
    }
}

// round 4
// speedup vs baseline: 1.4198x; 1.4198x over previous
#include <cuda_runtime.h>
#include <cuda_bf16.h>
#include <math.h>
#include <stdint.h>

// Problem constants
#define BATCH 2
#define DIM   256
#define HW    64
#define LSEQ  4096          // 64*64
#define BL    8192          // BATCH*LSEQ
#define DI    512           // d_inner
#define NST   16            // d_state
#define RNK   16            // dt_rank
#define XZW   1024          // 2*DI
#define HIDW  1024          // 4*DIM

// ---------------- scratch (static device globals; no allocation) -------------
__device__ float g_yn  [(size_t)BL * DIM];   // layernorm output (B,L,C)
__device__ float g_xz  [(size_t)BL * XZW];   // xz projection (xm | z)
__device__ float g_u   [(size_t)BL * DI];    // conv+silu output
__device__ float g_proj[(size_t)BL * 48];    // dt_raw(16) | B(16) | C(16)
__device__ float g_dt  [(size_t)BL * DI];    // softplus dt
__device__ float g_ym  [(size_t)BL * DI];    // scan output ys, then gated ym
__device__ float g_y2  [(size_t)BL * DIM];
__device__ float g_hid [(size_t)BL * HIDW];
__device__ float g_y3  [(size_t)BL * DIM];

// ---------------- transpose: in (B, D1, D2) -> out (B, D2, D1) ---------------
__global__ void k_transpose(const float* __restrict__ in, float* __restrict__ out,
                            int D1, int D2) {
    __shared__ float tile[32][33];
    int b  = blockIdx.z;
    int i0 = blockIdx.y * 32;   // along D1
    int j0 = blockIdx.x * 32;   // along D2
    int tx = threadIdx.x, ty = threadIdx.y;
    const float* ip = in  + (size_t)b * D1 * D2;
    float*       op = out + (size_t)b * D1 * D2;
#pragma unroll
    for (int s = 0; s < 32; s += 8)
        tile[ty + s][tx] = ip[(size_t)(i0 + ty + s) * D2 + j0 + tx];
    __syncthreads();
#pragma unroll
    for (int s = 0; s < 32; s += 8)
        op[(size_t)(j0 + ty + s) * D1 + i0 + tx] = tile[tx][ty + s];
}

// ---------------- layernorm (in place on (BL, 256) rows), warp per row -------
__global__ void k_layernorm(float* __restrict__ y,
                            const float* __restrict__ gamma,
                            const float* __restrict__ beta) {
    int gw   = (blockIdx.x * blockDim.x + threadIdx.x) >> 5;
    int lane = threadIdx.x & 31;
    if (gw >= BL) return;
    float* row = y + (size_t)gw * DIM;
    float v[8];
    float s = 0.f;
#pragma unroll
    for (int t = 0; t < 8; t++) { v[t] = row[lane + 32 * t]; s += v[t]; }
#pragma unroll
    for (int o = 16; o > 0; o >>= 1) s += __shfl_xor_sync(~0u, s, o);
    float mu = s * (1.f / DIM);
    float var = 0.f;
#pragma unroll
    for (int t = 0; t < 8; t++) { float d = v[t] - mu; var += d * d; }
#pragma unroll
    for (int o = 16; o > 0; o >>= 1) var += __shfl_xor_sync(~0u, var, o);
    float rstd = rsqrtf(var * (1.f / DIM) + 1e-5f);
#pragma unroll
    for (int t = 0; t < 8; t++) {
        int c = lane + 32 * t;
        row[c] = (v[t] - mu) * rstd * gamma[c] + beta[c];
    }
}

// ---------------- causal depthwise conv(4) + silu ----------------------------
__global__ void k_conv_silu(const float* __restrict__ xz,
                            const float* __restrict__ cw,
                            const float* __restrict__ cb,
                            float* __restrict__ u) {
    int i = blockIdx.x * blockDim.x + threadIdx.x;
    if (i >= BL * DI) return;
    int d    = i & (DI - 1);
    int lrow = i >> 9;          // (b*L + l)
    int l    = lrow & (LSEQ - 1);
    float acc = cb[d];
#pragma unroll
    for (int k = 0; k < 4; k++) {
        int ll = l - 3 + k;
        if (ll >= 0)
            acc += cw[d * 4 + k] * xz[(size_t)(lrow - 3 + k) * XZW + d];
    }
    u[i] = acc / (1.f + __expf(-acc));   // silu
}

// ---------------- x-proj: proj(BL,48) = u(BL,512) @ W_xp(48,512)^T ----------
__global__ void k_proj(const float* __restrict__ u,
                       const float* __restrict__ Wxp,
                       float* __restrict__ proj) {
    int gw   = (blockIdx.x * blockDim.x + threadIdx.x) >> 5;
    int lane = threadIdx.x & 31;
    if (gw >= BL) return;
    const float* ur = u + (size_t)gw * DI;
    float ureg[16];
#pragma unroll
    for (int t = 0; t < 16; t++) ureg[t] = ur[lane + 32 * t];
    for (int j = 0; j < 48; j++) {
        const float* w = Wxp + (size_t)j * DI;
        float s = 0.f;
#pragma unroll
        for (int t = 0; t < 16; t++) s += ureg[t] * w[lane + 32 * t];
#pragma unroll
        for (int o = 16; o > 0; o >>= 1) s += __shfl_xor_sync(~0u, s, o);
        if (lane == 0) proj[(size_t)gw * 48 + j] = s;
    }
}

// ---------------- dt = softplus(proj[:, :16] @ W_dt^T + b_dt) ----------------
__global__ void k_dt(const float* __restrict__ proj,
                     const float* __restrict__ Wdt,
                     const float* __restrict__ bdt,
                     float* __restrict__ dt) {
    __shared__ float p[16];
    int i = blockIdx.x;
    int d = threadIdx.x;
    if (d < 16) p[d] = proj[(size_t)i * 48 + d];
    __syncthreads();
    const float4* w4 = (const float4*)(Wdt + d * 16);
    float s = bdt[d];
#pragma unroll
    for (int r4 = 0; r4 < 4; r4++) {
        float4 w = w4[r4];
        s += p[r4 * 4 + 0] * w.x + p[r4 * 4 + 1] * w.y +
             p[r4 * 4 + 2] * w.z + p[r4 * 4 + 3] * w.w;
    }
    float sp = fmaxf(s, 0.f) + log1pf(__expf(-fabsf(s)));
    dt[(size_t)i * DI + d] = sp;
}

// ---------------- selective scan ---------------------------------------------
// thread = (b, d, n); block = 8 d-channels x 16 states; grid = B * DI/8
#define ST 128
__global__ void __launch_bounds__(128) k_scan(
    const float* __restrict__ dt, const float* __restrict__ u,
    const float* __restrict__ proj, const float* __restrict__ A_log,
    float* __restrict__ ys) {
    __shared__ float sdt[ST * 8], su[ST * 8], sB[ST * 16], sC[ST * 16], sy[ST * 8];
    int blk = blockIdx.x;
    int b   = blk >> 6;
    int d0  = (blk & 63) * 8;
    int tid  = threadIdx.x;
    int dloc = tid >> 4;
    int n    = tid & 15;
    int d    = d0 + dloc;
    float a = -__expf(A_log[d * NST + n]);
    float h = 0.f;
    size_t base = (size_t)b * LSEQ;
    for (int l0 = 0; l0 < LSEQ; l0 += ST) {
        __syncthreads();
        for (int idx = tid; idx < ST * 8; idx += 128) {
            int j = idx >> 3, dd = idx & 7;
            size_t g = (base + l0 + j) * DI + d0 + dd;
            sdt[idx] = dt[g];
            su[idx]  = u[g];
        }
        for (int idx = tid; idx < ST * 16; idx += 128) {
            int j = idx >> 4, nn = idx & 15;
            size_t g = (base + l0 + j) * 48;
            sB[idx] = proj[g + 16 + nn];
            sC[idx] = proj[g + 32 + nn];
        }
        __syncthreads();
#pragma unroll 4
        for (int j = 0; j < ST; j++) {
            float dtv = sdt[j * 8 + dloc];
            float dA  = __expf(dtv * a);
            h = dA * h + (dtv * su[j * 8 + dloc]) * sB[j * 16 + n];
            float yv = h * sC[j * 16 + n];
            yv += __shfl_xor_sync(~0u, yv, 8);
            yv += __shfl_xor_sync(~0u, yv, 4);
            yv += __shfl_xor_sync(~0u, yv, 2);
            yv += __shfl_xor_sync(~0u, yv, 1);
            if (n == 0) sy[j * 8 + dloc] = yv;
        }
        __syncthreads();
        for (int idx = tid; idx < ST * 8; idx += 128) {
            int j = idx >> 3, dd = idx & 7;
            ys[(base + l0 + j) * DI + d0 + dd] = sy[idx];
        }
    }
}

// ---------------- gate: ym = (ys + u*D) * silu(z) ----------------------------
__global__ void k_gate(float* __restrict__ ym, const float* __restrict__ u,
                       const float* __restrict__ xz, const float* __restrict__ Dv) {
    int i = blockIdx.x * blockDim.x + threadIdx.x;
    if (i >= BL * DI) return;
    int d   = i & (DI - 1);
    int row = i >> 9;
    float zv  = xz[(size_t)row * XZW + DI + d];
    float sil = zv / (1.f + __expf(-zv));
    ym[i] = (ym[i] + u[i] * Dv[d]) * sil;
}

// ================= TF32 tensor-core GEMM =====================================
// C(M,N) = A(M,K) @ Bw(N,K)^T (+ epilogue). K % 32 == 0, M % 128 == 0, N % 128 == 0.
// Block tile 128x128, 8 warps as 2(M) x 4(N), warp tile 64x32.
// mma.sync.aligned.m16n8k8.row.col.f32.tf32.tf32.f32
// EPI: 0 none; 1 bias+gelu; 2 +resid; 3 bias+resid

__device__ __forceinline__ uint32_t f2tf32(float x) {
    uint32_t u;
    asm("cvt.rna.tf32.f32 %0, %1;" : "=r"(u) : "f"(x));
    return u;
}

__device__ __forceinline__ void mma_tf32(float& c0, float& c1, float& c2, float& c3,
                                         uint32_t a0, uint32_t a1, uint32_t a2, uint32_t a3,
                                         uint32_t b0, uint32_t b1) {
    asm volatile(
        "mma.sync.aligned.m16n8k8.row.col.f32.tf32.tf32.f32 "
        "{%0,%1,%2,%3}, {%4,%5,%6,%7}, {%8,%9}, {%0,%1,%2,%3};"
        : "+f"(c0), "+f"(c1), "+f"(c2), "+f"(c3)
        : "r"(a0), "r"(a1), "r"(a2), "r"(a3), "r"(b0), "r"(b1));
}

template <int EPI>
__global__ void __launch_bounds__(256) k_tgemm(
    const float* __restrict__ A, const float* __restrict__ Bw,
    const float* __restrict__ bias, const float* __restrict__ resid,
    float* __restrict__ C, int M, int N, int K) {
    // smem: [row][36] pad-4 layout -> fragment LDS bank = (4*grp + l4) % 32, conflict-free
    __shared__ uint32_t As[128][36];
    __shared__ uint32_t Bs[128][36];

    int tid  = threadIdx.x;
    int lane = tid & 31;
    int wid  = tid >> 5;
    int wm   = wid & 1;        // 0..1  -> 64-row slab
    int wn   = wid >> 1;       // 0..3  -> 32-col slab
    int grp  = lane >> 2;      // 0..7
    int l4   = lane & 3;       // 0..3

    int row0 = blockIdx.y * 128;
    int col0 = blockIdx.x * 128;

    // gmem staging: 4 float4 per thread per array per K-tile
    int ldr[4], ldq[4];
#pragma unroll
    for (int f = 0; f < 4; f++) {
        int idx = tid + 256 * f;   // 0..1023
        ldr[f] = idx >> 3;         // 0..127
        ldq[f] = idx & 7;          // 0..7  (float4 index within 32-wide K tile)
    }

    float acc[4][4][4];
#pragma unroll
    for (int mi = 0; mi < 4; mi++)
#pragma unroll
        for (int ni = 0; ni < 4; ni++)
#pragma unroll
            for (int t = 0; t < 4; t++) acc[mi][ni][t] = 0.f;

    // prefetch first K-tile
    float4 ra[4], rb[4];
#pragma unroll
    for (int f = 0; f < 4; f++) {
        ra[f] = *(const float4*)(A  + (size_t)(row0 + ldr[f]) * K + ldq[f] * 4);
        rb[f] = *(const float4*)(Bw + (size_t)(col0 + ldr[f]) * K + ldq[f] * 4);
    }

    for (int kt = 0; kt < K; kt += 32) {
        // stage current tile into smem (with tf32 rounding)
#pragma unroll
        for (int f = 0; f < 4; f++) {
            uint4 va = make_uint4(f2tf32(ra[f].x), f2tf32(ra[f].y),
                                  f2tf32(ra[f].z), f2tf32(ra[f].w));
            uint4 vb = make_uint4(f2tf32(rb[f].x), f2tf32(rb[f].y),
                                  f2tf32(rb[f].z), f2tf32(rb[f].w));
            *(uint4*)&As[ldr[f]][ldq[f] * 4] = va;
            *(uint4*)&Bs[ldr[f]][ldq[f] * 4] = vb;
        }
        __syncthreads();

        // prefetch next tile
        if (kt + 32 < K) {
#pragma unroll
            for (int f = 0; f < 4; f++) {
                ra[f] = *(const float4*)(A  + (size_t)(row0 + ldr[f]) * K + kt + 32 + ldq[f] * 4);
                rb[f] = *(const float4*)(Bw + (size_t)(col0 + ldr[f]) * K + kt + 32 + ldq[f] * 4);
            }
        }

#pragma unroll
        for (int ks = 0; ks < 4; ks++) {
            int k0 = ks * 8;
            uint32_t af[4][4], bf[4][2];
#pragma unroll
            for (int mi = 0; mi < 4; mi++) {
                int r = wm * 64 + mi * 16 + grp;
                af[mi][0] = As[r][k0 + l4];
                af[mi][1] = As[r + 8][k0 + l4];
                af[mi][2] = As[r][k0 + l4 + 4];
                af[mi][3] = As[r + 8][k0 + l4 + 4];
            }
#pragma unroll
            for (int ni = 0; ni < 4; ni++) {
                int c = wn * 32 + ni * 8 + grp;
                bf[ni][0] = Bs[c][k0 + l4];
                bf[ni][1] = Bs[c][k0 + l4 + 4];
            }
#pragma unroll
            for (int mi = 0; mi < 4; mi++)
#pragma unroll
                for (int ni = 0; ni < 4; ni++)
                    mma_tf32(acc[mi][ni][0], acc[mi][ni][1], acc[mi][ni][2], acc[mi][ni][3],
                             af[mi][0], af[mi][1], af[mi][2], af[mi][3],
                             bf[ni][0], bf[ni][1]);
        }
        __syncthreads();
    }

    // epilogue
#pragma unroll
    for (int mi = 0; mi < 4; mi++) {
#pragma unroll
        for (int ni = 0; ni < 4; ni++) {
            int r  = row0 + wm * 64 + mi * 16 + grp;
            int c  = col0 + wn * 32 + ni * 8 + l4 * 2;
#pragma unroll
            for (int half = 0; half < 2; half++) {
                int rr = r + half * 8;
                float v0 = acc[mi][ni][half * 2 + 0];
                float v1 = acc[mi][ni][half * 2 + 1];
                if (EPI == 1) {
                    v0 += bias[c];     v1 += bias[c + 1];
                    v0 = 0.5f * v0 * (1.f + erff(v0 * 0.70710678118654752f));
                    v1 = 0.5f * v1 * (1.f + erff(v1 * 0.70710678118654752f));
                } else if (EPI == 2) {
                    const float2 rv = *(const float2*)(resid + (size_t)rr * N + c);
                    v0 += rv.x; v1 += rv.y;
                } else if (EPI == 3) {
                    const float2 rv = *(const float2*)(resid + (size_t)rr * N + c);
                    v0 += bias[c] + rv.x; v1 += bias[c + 1] + rv.y;
                }
                float2 ov = make_float2(v0, v1);
                *(float2*)(C + (size_t)rr * N + c) = ov;
            }
        }
    }
}

// ---------------- launcher ---------------------------------------------------
extern "C" void kernel_launch(void* const* d_in, const int* in_sizes, int n_in,
                              void* d_out, int out_size) {
    const float* x      = (const float*)d_in[0];
    const float* gamma  = (const float*)d_in[1];
    const float* beta   = (const float*)d_in[2];
    const float* W_in   = (const float*)d_in[3];
    const float* conv_w = (const float*)d_in[4];
    const float* conv_b = (const float*)d_in[5];
    const float* W_xp   = (const float*)d_in[6];
    const float* W_dt   = (const float*)d_in[7];
    const float* b_dt   = (const float*)d_in[8];
    const float* A_log  = (const float*)d_in[9];
    const float* Dv     = (const float*)d_in[10];
    const float* W_out  = (const float*)d_in[11];
    const float* W1     = (const float*)d_in[12];
    const float* b1     = (const float*)d_in[13];
    const float* W2     = (const float*)d_in[14];
    const float* b2     = (const float*)d_in[15];
    float* out = (float*)d_out;

    float *yn, *xz, *u, *proj, *dt, *ym, *y2, *hid, *y3;
    cudaGetSymbolAddress((void**)&yn,  g_yn);
    cudaGetSymbolAddress((void**)&xz,  g_xz);
    cudaGetSymbolAddress((void**)&u,   g_u);
    cudaGetSymbolAddress((void**)&proj,g_proj);
    cudaGetSymbolAddress((void**)&dt,  g_dt);
    cudaGetSymbolAddress((void**)&ym,  g_ym);
    cudaGetSymbolAddress((void**)&y2,  g_y2);
    cudaGetSymbolAddress((void**)&hid, g_hid);
    cudaGetSymbolAddress((void**)&y3,  g_y3);

    dim3 tb(32, 8);

    // 1) transpose x (B,C,L) -> yn (B,L,C)
    {
        dim3 grid(LSEQ / 32, DIM / 32, BATCH);
        k_transpose<<<grid, tb>>>(x, yn, DIM, LSEQ);
    }
    // 2) layernorm in place
    k_layernorm<<<BL * 32 / 256, 256>>>(yn, gamma, beta);
    // 3) xz = yn @ W_in^T  (8192 x 1024 x 256)
    {
        dim3 grid(XZW / 128, BL / 128);
        k_tgemm<0><<<grid, 256>>>(yn, W_in, nullptr, nullptr, xz, BL, XZW, DIM);
    }
    // 4) conv + silu -> u
    k_conv_silu<<<(BL * DI) / 256, 256>>>(xz, conv_w, conv_b, u);
    // 5) proj = u @ W_xp^T
    k_proj<<<BL / 8, 256>>>(u, W_xp, proj);
    // 6) dt
    k_dt<<<BL, DI>>>(proj, W_dt, b_dt, dt);
    // 7) selective scan -> ym (holds ys)
    k_scan<<<BATCH * (DI / 8), 128>>>(dt, u, proj, A_log, ym);
    // 8) gate
    k_gate<<<(BL * DI) / 256, 256>>>(ym, u, xz, Dv);
    // 9) y2 = ym @ W_out^T + yn   (8192 x 256 x 512)
    {
        dim3 grid(DIM / 128, BL / 128);
        k_tgemm<2><<<grid, 256>>>(ym, W_out, nullptr, yn, y2, BL, DIM, DI);
    }
    // 10) hid = gelu(y2 @ W1^T + b1)   (8192 x 1024 x 256)
    {
        dim3 grid(HIDW / 128, BL / 128);
        k_tgemm<1><<<grid, 256>>>(y2, W1, b1, nullptr, hid, BL, HIDW, DIM);
    }
    // 11) y3 = hid @ W2^T + b2 + y2   (8192 x 256 x 1024)
    {
        dim3 grid(DIM / 128, BL / 128);
        k_tgemm<3><<<grid, 256>>>(hid, W2, b2, y2, y3, BL, DIM, HIDW);
    }
    // 12) transpose y3 (B,L,C) -> out (B,C,L)
    {
        dim3 grid(DIM / 32, LSEQ / 32, BATCH);
        k_transpose<<<grid, tb>>>(y3, out, LSEQ, DIM);
    }
}